// round 12
// baseline (speedup 1.0000x reference)
#include <cuda_runtime.h>
#include <math.h>

#define CH 24          // b*c independent planes
#define HI 192
#define WI 192
#define NI 186         // interior rows/cols
#define RINGROWS 64
#define NBLK 6         // CTAs per plane
#define WARPS 4        // 1 warp per SMSP: 144 CTAs x 128thr -> 1 CTA/SM, no issue sharing
#define THREADS (WARPS*32)

typedef unsigned long long ull;

__device__ float  g_ring[CH * RINGROWS * WI];   // zero-padded delta rows (rows w>=1 published)
__device__ int    g_prog[CH * WI];              // per-row completed-column counters
__device__ double g_sumsq;
__device__ unsigned g_done;

__device__ __forceinline__ int ldAcqG(const int* p) {
    int v;
    asm volatile("ld.acquire.gpu.global.b32 %0, [%1];" : "=r"(v) : "l"(p) : "memory");
    return v;
}
__device__ __forceinline__ void stRelG(int* p, int v) {
    asm volatile("st.release.gpu.global.b32 [%0], %1;" :: "l"(p), "r"(v) : "memory");
}
__device__ __forceinline__ int ldAcqS(unsigned a) {
    int v;
    asm volatile("ld.acquire.cta.shared.b32 %0, [%1];" : "=r"(v) : "r"(a) : "memory");
    return v;
}
__device__ __forceinline__ void stRelS(unsigned a, int v) {
    asm volatile("st.release.cta.shared.b32 [%0], %1;" :: "r"(a), "r"(v) : "memory");
}
__device__ __forceinline__ void fma2(ull& d, ull a, ull b) {
    asm("fma.rn.f32x2 %0, %1, %2, %0;" : "+l"(d) : "l"(a), "l"(b));
}
__device__ __forceinline__ float hsum2(ull v) {
    float lo, hi;
    asm("mov.b64 {%0, %1}, %2;" : "=f"(lo), "=f"(hi) : "l"(v));
    return lo + hi;
}
__device__ __forceinline__ ull packf2(float lo, float hi) {
    ull r;
    asm("mov.b64 %0, {%1, %2};" : "=l"(r) : "f"(lo), "f"(hi));
    return r;
}
// tanh(x) = 1 - 2/(e^{2x}+1); abs err ~1e-6
__device__ __forceinline__ float ftanh(float x) {
    float e = __expf(2.0f * x);
    float r;
    asm("rcp.approx.f32 %0, %1;" : "=f"(r) : "f"(e + 1.0f));
    return fmaf(-2.0f, r, 1.0f);
}

__global__ void zero_kernel() {
    int idx = blockIdx.x * blockDim.x + threadIdx.x;
    int stride = gridDim.x * blockDim.x;
    const int n = CH * RINGROWS * WI;
    for (int i = idx; i < n; i += stride) g_ring[i] = 0.0f;
    for (int i = idx; i < CH * WI; i += stride) g_prog[i] = 0;
    if (idx == 0) { g_sumsq = 0.0; g_done = 0; }
}

__global__ __launch_bounds__(THREADS, 1)
void codec_kernel(const float* __restrict__ x,
                  const float* __restrict__ W1, const float* __restrict__ B1,
                  const float* __restrict__ W2, const float* __restrict__ B2,
                  const float* __restrict__ W3, const float* __restrict__ B3,
                  const float* __restrict__ W4, const float* __restrict__ B4,
                  float* __restrict__ out)
{
    // All weights staged in shared (k-major interleaved float4 pairs);
    // W1 chunks 0..7 additionally mirrored in registers (48 ull/lane).
    __shared__ __align__(16) ulonglong2 sW1q[12 * 96];
    __shared__ __align__(16) ulonglong2 sW2q[24 * 24];
    __shared__ __align__(16) ulonglong2 sW3q[6 * 12];
    __shared__ float sB1[96], sB2[24], sB3[12], sW4[12];
    __shared__ float sB4v;
    __shared__ __align__(16) float sFeat[WARPS][48];
    __shared__ __align__(16) float sH1[WARPS][96];
    __shared__ __align__(16) float sH2[WARPS][24];
    __shared__ __align__(16) float sRing[WARPS][WI];   // per-warp current row deltas
    __shared__ int sProg[WARPS];

    const int tid = threadIdx.x;

    {
        float* f1 = (float*)sW1q;
        for (int idx = tid; idx < 48 * 96; idx += THREADS) {
            int k = idx / 96, m = idx % 96;
            f1[((k >> 2) * 96 + m) * 4 + (k & 3)] = W1[idx];
        }
        float* f2 = (float*)sW2q;
        for (int idx = tid; idx < 96 * 24; idx += THREADS) {
            int k = idx / 24, m = idx % 24;
            f2[((k >> 2) * 24 + m) * 4 + (k & 3)] = W2[idx];
        }
        float* f3 = (float*)sW3q;
        for (int idx = tid; idx < 24 * 12; idx += THREADS) {
            int k = idx / 12, m = idx % 12;
            f3[((k >> 2) * 12 + m) * 4 + (k & 3)] = W3[idx];
        }
    }
    if (tid < 96) sB1[tid] = B1[tid];
    if (tid < 24) sB2[tid] = B2[tid];
    if (tid < 12) sB3[tid] = B3[tid];
    if (tid < 12) sW4[tid] = W4[tid];
    if (tid == 0) sB4v = B4[0];
    for (int idx = tid; idx < WARPS * WI; idx += THREADS) ((float*)sRing)[idx] = 0.0f;
    if (tid < WARPS) sProg[tid] = 0;
    __syncthreads();

    const int ch   = blockIdx.x / NBLK;
    const int blk  = blockIdx.x % NBLK;
    const int w    = tid >> 5;
    const int lane = tid & 31;

    const float* xch    = x + ch * HI * WI;
    float*       ringCh = g_ring + ch * RINGROWS * WI;
    int*         progCh = g_prog + ch * WI;

    const unsigned sprogAddr = (unsigned)__cvta_generic_to_shared(&sProg[0]);
    const unsigned sprogOwn  = sprogAddr + w * 4;
    const unsigned sprogPrev = sprogAddr + (w - 1) * 4;

    float* featw = sFeat[w];
    float* h1w   = sH1[w];
    float* h2w   = sH2[w];

    const int m0 = lane, m1 = lane + 32, m2 = lane + 64;
    const float bb0 = sB1[m0], bb1 = sB1[m1], bb2 = sB1[m2];
    const float b2l = (lane < 24) ? sB2[lane] : 0.0f;
    const float b3l = (lane < 12) ? sB3[lane] : 0.0f;
    const float w4l = (lane < 12) ? sW4[lane] : 0.0f;
    const float b4v = sB4v;

    // ---- W1 chunks 0..7 (k=0..31) in registers: 48 packed f32x2 per lane ----
    ull w1r[48];
    #pragma unroll
    for (int k4 = 0; k4 < 8; ++k4) {
        #pragma unroll
        for (int mi = 0; mi < 3; ++mi) {
            int m = lane + 32 * mi;
            int k = 4 * k4;
            w1r[k4 * 6 + mi * 2 + 0] = packf2(__ldg(W1 + (k + 0) * 96 + m), __ldg(W1 + (k + 1) * 96 + m));
            w1r[k4 * 6 + mi * 2 + 1] = packf2(__ldg(W1 + (k + 2) * 96 + m), __ldg(W1 + (k + 3) * 96 + m));
        }
    }

    // ---- static tap descriptors ----
    // feats 0..23: image taps; feats 24..31 (lanes 24..31): s=lane-24 -> dy = s==7 ? 1 : 0, dx;
    // feats 32..44 (lanes 0..12): s=lane+8 -> dy=s/7 (1 or 2), dx=s%7;
    // feats 45..47 (lanes 13..15): own last-3 deltas from registers.
    int p1_dy = 0, p1_dx = 0;
    if (lane >= 24) { int s = lane - 24; p1_dy = (s == 7) ? 1 : 0; p1_dx = (s == 7) ? 0 : s; }
    int p2_dy = 0, p2_dx = 0;
    if (lane < 13) { int s = lane + 8; p2_dy = s / 7; p2_dx = s % 7; }

    double sumsqd = 0.0;

    for (int i = WARPS * blk + w; i < NI; i += NBLK * WARPS) {
        const float* imgP = nullptr;
        if (lane < 21)      imgP = xch + (i + lane / 7) * WI + (lane % 7);
        else if (lane < 24) imgP = xch + (i + 3) * WI + (lane - 21);

        // tap row local index l = w-3+dy: l>=0 -> own-CTA sRing[l]; else global ring
        const float* base1 = nullptr; bool tapG1 = false;
        if (lane >= 24) {
            int l = w - 3 + p1_dy;
            if (l >= 0) base1 = &sRing[l][p1_dx];
            else { base1 = ringCh + ((unsigned)(i - 3 + p1_dy) & (RINGROWS - 1)) * WI + p1_dx; tapG1 = true; }
        }
        const float* base2 = nullptr; bool tapG2 = false;
        if (lane < 13) {
            int l = w - 3 + p2_dy;
            if (l >= 0) base2 = &sRing[l][p2_dx];
            else { base2 = ringCh + ((unsigned)(i - 3 + p2_dy) & (RINGROWS - 1)) * WI + p2_dx; tapG2 = true; }
        }

        // wavefront sync sources: single shared poll for w>=1; three global polls for w=0
        int c1 = NI + 8, c2 = NI + 8, c3 = NI + 8;
        const int *gp1 = nullptr, *gp2 = nullptr, *gp3 = nullptr;
        if (w == 0) {
            if (i - 1 >= 0) { gp1 = progCh + (i - 1); c1 = 0; }
            if (i - 2 >= 0) { gp2 = progCh + (i - 2); c2 = 0; }
            if (i - 3 >= 0) { gp3 = progCh + (i - 3); c3 = 0; }
        }
        const int  sNeedBase = (i - 1) * 256;
        const int  rowTag    = i * 256;
        int*       progMe    = progCh + i;
        float*     ringW     = ringCh + ((unsigned)i & (RINGROWS - 1)) * WI;
        const float* tgtRow  = xch + (i + 3) * WI + 3;
        const bool pubG      = (w >= WARPS - 3);   // rows consumed by the next CTA

        int   spc = 0;
        float d0 = 0.0f, d1 = 0.0f, d2 = 0.0f;   // deltas j-3, j-2, j-1 (all lanes)
        float rowsum = 0.0f;

        for (int j = 0; j < NI; ++j) {
            int nd = j + 4; if (nd > NI) nd = NI;
            // ---- wavefront wait ----
            if (w) {
                int sneed = sNeedBase + nd;
                while (spc < sneed) spc = ldAcqS(sprogPrev);
            } else {
                while (c1 < nd) c1 = ldAcqG(gp1);
                while (c2 < nd) c2 = ldAcqG(gp2);
                while (c3 < nd) c3 = ldAcqG(gp3);
            }

            // ---- gather 48 features into shared staging ----
            float v1;
            if (lane < 24)  v1 = __ldg(imgP + j);
            else if (tapG1) v1 = __ldcg(base1 + j);
            else            v1 = base1[j];
            featw[lane] = v1;
            if (lane < 13)       featw[lane + 32] = tapG2 ? __ldcg(base2 + j) : base2[j];
            else if (lane < 16)  featw[lane + 32] = (lane == 13) ? d0 : (lane == 14) ? d1 : d2;
            __syncwarp();
            float tgt = __ldg(tgtRow + j);   // broadcast

            // ---- layer 1: 48 -> 96; chunks 0..7 reg weights, chunks 8..11 shared ----
            ull a00 = 0, a01 = 0, a10 = 0, a11 = 0, a20 = 0, a21 = 0;
            {
                const ulonglong2* F2 = (const ulonglong2*)featw;
                #pragma unroll
                for (int k4 = 0; k4 < 8; ++k4) {
                    ulonglong2 f = F2[k4];
                    fma2(a00, f.x, w1r[k4 * 6 + 0]); fma2(a01, f.y, w1r[k4 * 6 + 1]);
                    fma2(a10, f.x, w1r[k4 * 6 + 2]); fma2(a11, f.y, w1r[k4 * 6 + 3]);
                    fma2(a20, f.x, w1r[k4 * 6 + 4]); fma2(a21, f.y, w1r[k4 * 6 + 5]);
                }
                #pragma unroll
                for (int k4 = 8; k4 < 12; ++k4) {
                    ulonglong2 f  = F2[k4];
                    ulonglong2 wa = sW1q[k4 * 96 + m0];
                    ulonglong2 wb = sW1q[k4 * 96 + m1];
                    ulonglong2 wc = sW1q[k4 * 96 + m2];
                    fma2(a00, f.x, wa.x); fma2(a01, f.y, wa.y);
                    fma2(a10, f.x, wb.x); fma2(a11, f.y, wb.y);
                    fma2(a20, f.x, wc.x); fma2(a21, f.y, wc.y);
                }
            }
            h1w[m0] = ftanh(bb0 + hsum2(a00) + hsum2(a01));
            h1w[m1] = ftanh(bb1 + hsum2(a10) + hsum2(a11));
            h1w[m2] = ftanh(bb2 + hsum2(a20) + hsum2(a21));
            __syncwarp();

            // ---- layer 2: 96 -> 24 (lanes 0..23), shared weights ----
            if (lane < 24) {
                ull a0 = 0, a1 = 0, a2 = 0, a3 = 0;
                const ulonglong2* H = (const ulonglong2*)h1w;
                #pragma unroll
                for (int k4 = 0; k4 < 24; k4 += 2) {
                    ulonglong2 h  = H[k4];
                    ulonglong2 wv = sW2q[k4 * 24 + lane];
                    fma2(a0, h.x, wv.x); fma2(a1, h.y, wv.y);
                    ulonglong2 h2  = H[k4 + 1];
                    ulonglong2 wv2 = sW2q[(k4 + 1) * 24 + lane];
                    fma2(a2, h2.x, wv2.x); fma2(a3, h2.y, wv2.y);
                }
                float v = b2l + (hsum2(a0) + hsum2(a1)) + (hsum2(a2) + hsum2(a3));
                h2w[lane] = ftanh(v);
            }
            __syncwarp();

            // ---- layer 3: 24 -> 12 (lanes 0..11) + layer 4 dot-12 ----
            float pr = 0.0f;
            if (lane < 12) {
                ull a0 = 0, a1 = 0;
                const ulonglong2* H3 = (const ulonglong2*)h2w;
                #pragma unroll
                for (int k4 = 0; k4 < 6; ++k4) {
                    ulonglong2 h  = H3[k4];
                    ulonglong2 wv = sW3q[k4 * 12 + lane];
                    fma2(a0, h.x, wv.x); fma2(a1, h.y, wv.y);
                }
                pr = ftanh(b3l + hsum2(a0) + hsum2(a1)) * w4l;
            }
            pr += __shfl_xor_sync(0xffffffffu, pr, 16);
            pr += __shfl_xor_sync(0xffffffffu, pr, 8);
            pr += __shfl_xor_sync(0xffffffffu, pr, 4);
            pr += __shfl_xor_sync(0xffffffffu, pr, 2);
            pr += __shfl_xor_sync(0xffffffffu, pr, 1);

            float out_v = ftanh(pr + b4v);
            float delta = tgt - out_v;            // every lane computes delta
            d0 = d1; d1 = d2; d2 = delta;

            if (lane == 0) {
                rowsum = fmaf(delta, delta, rowsum);
                sRing[w][3 + j] = delta;                  // own-row ring (shared)
                stRelS(sprogOwn, rowTag + j + 1);         // local release flag
                if (pubG) {
                    ringW[3 + j] = delta;                 // global ring for next-CTA consumers
                    stRelG(progMe, j + 1);
                }
            }
            __syncwarp();
        }
        if (lane == 0) sumsqd += (double)rowsum;
    }
    if (lane == 0) atomicAdd(&g_sumsq, sumsqd);

    // ---- fused finish: last CTA writes the output ----
    __syncthreads();
    if (tid == 0) {
        __threadfence();
        unsigned prev = atomicAdd(&g_done, 1u);
        if (prev == (unsigned)(CH * NBLK - 1)) {
            __threadfence();
            double s = *((volatile double*)&g_sumsq);
            out[0] = (float)sqrt(s / 875520.0);   // b*c*(h-2)*w = 8*3*190*192
        }
    }
}

extern "C" void kernel_launch(void* const* d_in, const int* in_sizes, int n_in,
                              void* d_out, int out_size) {
    const float* x  = (const float*)d_in[0];
    const float* W1 = (const float*)d_in[1];
    const float* b1 = (const float*)d_in[2];
    const float* W2 = (const float*)d_in[3];
    const float* b2 = (const float*)d_in[4];
    const float* W3 = (const float*)d_in[5];
    const float* b3 = (const float*)d_in[6];
    const float* W4 = (const float*)d_in[7];
    const float* b4 = (const float*)d_in[8];

    zero_kernel<<<512, 256>>>();
    codec_kernel<<<CH * NBLK, THREADS>>>(x, W1, b1, W2, b2, W3, b3, W4, b4, (float*)d_out);
}

// round 13
// speedup vs baseline: 2.4921x; 2.4921x over previous
#include <cuda_runtime.h>
#include <math.h>

#define CH 24          // b*c independent planes
#define HI 192
#define WI 192
#define NI 186         // interior rows/cols
#define RINGROWS 64
#define NBLK 6         // CTAs per plane
#define WARPS 8
#define THREADS (WARPS*32)
#define REALCTAS (CH*NBLK)   // 144
#define GRIDSZ 148           // >=148 to disarm low-grid issue throttle

typedef unsigned long long ull;

__device__ float  g_ring[CH * RINGROWS * WI];   // zero-padded delta rows (rows w>=5 published)
__device__ int    g_prog[CH * WI];              // per-row completed-column counters
__device__ double g_sumsq;
__device__ unsigned g_done;

__device__ __forceinline__ int ldAcqG(const int* p) {
    int v;
    asm volatile("ld.acquire.gpu.global.b32 %0, [%1];" : "=r"(v) : "l"(p) : "memory");
    return v;
}
__device__ __forceinline__ void stRelG(int* p, int v) {
    asm volatile("st.release.gpu.global.b32 [%0], %1;" :: "l"(p), "r"(v) : "memory");
}
__device__ __forceinline__ int ldAcqS(unsigned a) {
    int v;
    asm volatile("ld.acquire.cta.shared.b32 %0, [%1];" : "=r"(v) : "r"(a) : "memory");
    return v;
}
__device__ __forceinline__ void stRelS(unsigned a, int v) {
    asm volatile("st.release.cta.shared.b32 [%0], %1;" :: "r"(a), "r"(v) : "memory");
}
__device__ __forceinline__ void fma2(ull& d, ull a, ull b) {
    asm("fma.rn.f32x2 %0, %1, %2, %0;" : "+l"(d) : "l"(a), "l"(b));
}
__device__ __forceinline__ float hsum2(ull v) {
    float lo, hi;
    asm("mov.b64 {%0, %1}, %2;" : "=f"(lo), "=f"(hi) : "l"(v));
    return lo + hi;
}
__device__ __forceinline__ ull packf2(float lo, float hi) {
    ull r;
    asm("mov.b64 %0, {%1, %2};" : "=l"(r) : "f"(lo), "f"(hi));
    return r;
}
// tanh(x) = 1 - 2/(e^{2x}+1); abs err ~1e-6
__device__ __forceinline__ float ftanh(float x) {
    float e = __expf(2.0f * x);
    float r;
    asm("rcp.approx.f32 %0, %1;" : "=f"(r) : "f"(e + 1.0f));
    return fmaf(-2.0f, r, 1.0f);
}

__global__ void zero_kernel() {
    int idx = blockIdx.x * blockDim.x + threadIdx.x;
    int stride = gridDim.x * blockDim.x;
    const int n = CH * RINGROWS * WI;
    for (int i = idx; i < n; i += stride) g_ring[i] = 0.0f;
    for (int i = idx; i < CH * WI; i += stride) g_prog[i] = 0;
    if (idx == 0) { g_sumsq = 0.0; g_done = 0; }
}

__global__ __launch_bounds__(THREADS, 1)
void codec_kernel(const float* __restrict__ x,
                  const float* __restrict__ W1, const float* __restrict__ B1,
                  const float* __restrict__ W2, const float* __restrict__ B2,
                  const float* __restrict__ W3, const float* __restrict__ B3,
                  const float* __restrict__ W4, const float* __restrict__ B4,
                  float* __restrict__ out)
{
    if (blockIdx.x >= REALCTAS) return;   // throttle-disarm dummies

    // All weights staged in shared (k-major interleaved float4 pairs);
    // W1 chunks 0..7 additionally mirrored in registers (48 ull/lane).
    // W2/W3 lane-padded to 32 (zero weights) so L2/L3 run branchless on all lanes.
    __shared__ __align__(16) ulonglong2 sW1q[12 * 96];
    __shared__ __align__(16) ulonglong2 sW2q[24 * 32];
    __shared__ __align__(16) ulonglong2 sW3q[6 * 32];
    __shared__ float sB1[96], sB2[32], sB3[12], sW4[12];
    __shared__ float sB4v;
    __shared__ __align__(16) float sFeat[WARPS][48];
    __shared__ __align__(16) float sH1[WARPS][96];
    __shared__ __align__(16) float sH2[WARPS][32];
    __shared__ __align__(16) float sRing[WARPS][WI];   // per-warp current row deltas
    __shared__ int sProg[WARPS];

    const int tid = threadIdx.x;

    {
        float* f1 = (float*)sW1q;
        for (int idx = tid; idx < 48 * 96; idx += THREADS) {
            int k = idx / 96, m = idx % 96;
            f1[((k >> 2) * 96 + m) * 4 + (k & 3)] = W1[idx];
        }
        float* f2 = (float*)sW2q;
        for (int idx = tid; idx < 96 * 32; idx += THREADS) {
            int k = idx / 32, m = idx % 32;
            f2[((k >> 2) * 32 + m) * 4 + (k & 3)] = (m < 24) ? W2[k * 24 + m] : 0.0f;
        }
        float* f3 = (float*)sW3q;
        for (int idx = tid; idx < 24 * 32; idx += THREADS) {
            int k = idx / 32, m = idx % 32;
            f3[((k >> 2) * 32 + m) * 4 + (k & 3)] = (m < 12) ? W3[k * 12 + m] : 0.0f;
        }
    }
    if (tid < 96) sB1[tid] = B1[tid];
    if (tid < 32) sB2[tid] = (tid < 24) ? B2[tid] : 0.0f;
    if (tid < 12) sB3[tid] = B3[tid];
    if (tid < 12) sW4[tid] = W4[tid];
    if (tid == 0) sB4v = B4[0];
    for (int idx = tid; idx < WARPS * WI; idx += THREADS) ((float*)sRing)[idx] = 0.0f;
    if (tid < WARPS) sProg[tid] = 0;
    __syncthreads();

    const int ch   = blockIdx.x / NBLK;
    const int blk  = blockIdx.x % NBLK;
    const int w    = tid >> 5;
    const int lane = tid & 31;

    const float* xch    = x + ch * HI * WI;
    float*       ringCh = g_ring + ch * RINGROWS * WI;
    int*         progCh = g_prog + ch * WI;

    const unsigned sprogAddr = (unsigned)__cvta_generic_to_shared(&sProg[0]);
    const unsigned sprogOwn  = sprogAddr + w * 4;
    const unsigned sprogPrev = sprogAddr + (w - 1) * 4;

    float* featw = sFeat[w];
    float* h1w   = sH1[w];
    float* h2w   = sH2[w];

    const int m0 = lane, m1 = lane + 32, m2 = lane + 64;
    const float bb0 = sB1[m0], bb1 = sB1[m1], bb2 = sB1[m2];
    const float b2l = sB2[lane];
    const float b3l = (lane < 12) ? sB3[lane] : 0.0f;
    const float w4l = (lane < 12) ? sW4[lane] : 0.0f;
    const float b4v = sB4v;

    // ---- W1 chunks 0..7 (k=0..31) in registers: 48 packed f32x2 per lane ----
    ull w1r[48];
    #pragma unroll
    for (int k4 = 0; k4 < 8; ++k4) {
        #pragma unroll
        for (int mi = 0; mi < 3; ++mi) {
            int m = lane + 32 * mi;
            int k = 4 * k4;
            w1r[k4 * 6 + mi * 2 + 0] = packf2(__ldg(W1 + (k + 0) * 96 + m), __ldg(W1 + (k + 1) * 96 + m));
            w1r[k4 * 6 + mi * 2 + 1] = packf2(__ldg(W1 + (k + 2) * 96 + m), __ldg(W1 + (k + 3) * 96 + m));
        }
    }

    // ---- static tap descriptors ----
    int p1_dy = 0, p1_dx = 0;
    if (lane >= 24) { int s = lane - 24; p1_dy = (s == 7) ? 1 : 0; p1_dx = (s == 7) ? 0 : s; }
    int p2_dy = 0, p2_dx = 0;
    if (lane < 13) { int s = lane + 8; p2_dy = s / 7; p2_dx = s % 7; }

    double sumsqd = 0.0;

    for (int i = WARPS * blk + w; i < NI; i += NBLK * WARPS) {
        const float* imgP = nullptr;
        if (lane < 21)      imgP = xch + (i + lane / 7) * WI + (lane % 7);
        else if (lane < 24) imgP = xch + (i + 3) * WI + (lane - 21);

        const float* base1 = nullptr; bool tapG1 = false;
        if (lane >= 24) {
            int l = w - 3 + p1_dy;
            if (l >= 0) base1 = &sRing[l][p1_dx];
            else { base1 = ringCh + ((unsigned)(i - 3 + p1_dy) & (RINGROWS - 1)) * WI + p1_dx; tapG1 = true; }
        }
        const float* base2 = nullptr; bool tapG2 = false;
        if (lane < 13) {
            int l = w - 3 + p2_dy;
            if (l >= 0) base2 = &sRing[l][p2_dx];
            else { base2 = ringCh + ((unsigned)(i - 3 + p2_dy) & (RINGROWS - 1)) * WI + p2_dx; tapG2 = true; }
        }

        int c1 = NI + 8, c2 = NI + 8, c3 = NI + 8;
        const int *gp1 = nullptr, *gp2 = nullptr, *gp3 = nullptr;
        if (w == 0) {
            if (i - 1 >= 0) { gp1 = progCh + (i - 1); c1 = 0; }
            if (i - 2 >= 0) { gp2 = progCh + (i - 2); c2 = 0; }
            if (i - 3 >= 0) { gp3 = progCh + (i - 3); c3 = 0; }
        }
        const int  sNeedBase = (i - 1) * 256;
        const int  rowTag    = i * 256;
        int*       progMe    = progCh + i;
        float*     ringW     = ringCh + ((unsigned)i & (RINGROWS - 1)) * WI;
        const float* tgtRow  = xch + (i + 3) * WI + 3;
        const bool pubG      = (w >= WARPS - 3);

        int   spc = 0;
        float d0 = 0.0f, d1 = 0.0f, d2 = 0.0f;   // deltas j-3, j-2, j-1
        float rowsum = 0.0f;

        for (int j = 0; j < NI; ++j) {
            // ---- hoisted independent loads (before poll) ----
            float vimg = 0.0f;
            if (lane < 24) vimg = __ldg(imgP + j);
            float tgt = __ldg(tgtRow + j);

            int nd = j + 4; if (nd > NI) nd = NI;
            // ---- wavefront wait ----
            if (w) {
                int sneed = sNeedBase + nd;
                while (spc < sneed) spc = ldAcqS(sprogPrev);
            } else {
                while (c1 < nd) c1 = ldAcqG(gp1);
                while (c2 < nd) c2 = ldAcqG(gp2);
                while (c3 < nd) c3 = ldAcqG(gp3);
            }

            // ---- gather 48 features into shared staging ----
            float v1;
            if (lane < 24)  v1 = vimg;
            else if (tapG1) v1 = __ldcg(base1 + j);
            else            v1 = base1[j];
            featw[lane] = v1;
            if (lane < 13)       featw[lane + 32] = tapG2 ? __ldcg(base2 + j) : base2[j];
            else if (lane < 16)  featw[lane + 32] = (lane == 13) ? d0 : (lane == 14) ? d1 : d2;
            __syncwarp();

            // ---- layer 1: 48 -> 96; chunks 0..7 reg weights, chunks 8..11 shared ----
            ull a00 = 0, a01 = 0, a10 = 0, a11 = 0, a20 = 0, a21 = 0;
            {
                const ulonglong2* F2 = (const ulonglong2*)featw;
                #pragma unroll
                for (int k4 = 0; k4 < 8; ++k4) {
                    ulonglong2 f = F2[k4];
                    fma2(a00, f.x, w1r[k4 * 6 + 0]); fma2(a01, f.y, w1r[k4 * 6 + 1]);
                    fma2(a10, f.x, w1r[k4 * 6 + 2]); fma2(a11, f.y, w1r[k4 * 6 + 3]);
                    fma2(a20, f.x, w1r[k4 * 6 + 4]); fma2(a21, f.y, w1r[k4 * 6 + 5]);
                }
                #pragma unroll
                for (int k4 = 8; k4 < 12; ++k4) {
                    ulonglong2 f  = F2[k4];
                    ulonglong2 wa = sW1q[k4 * 96 + m0];
                    ulonglong2 wb = sW1q[k4 * 96 + m1];
                    ulonglong2 wc = sW1q[k4 * 96 + m2];
                    fma2(a00, f.x, wa.x); fma2(a01, f.y, wa.y);
                    fma2(a10, f.x, wb.x); fma2(a11, f.y, wb.y);
                    fma2(a20, f.x, wc.x); fma2(a21, f.y, wc.y);
                }
            }
            h1w[m0] = ftanh(bb0 + hsum2(a00) + hsum2(a01));
            h1w[m1] = ftanh(bb1 + hsum2(a10) + hsum2(a11));
            h1w[m2] = ftanh(bb2 + hsum2(a20) + hsum2(a21));
            __syncwarp();

            // ---- layer 2: 96 -> 24, branchless (all 32 lanes; lanes>=24 use zero weights) ----
            {
                ull a0 = 0, a1 = 0, a2 = 0, a3 = 0;
                const ulonglong2* H = (const ulonglong2*)h1w;
                #pragma unroll
                for (int k4 = 0; k4 < 24; k4 += 2) {
                    ulonglong2 h  = H[k4];
                    ulonglong2 wv = sW2q[k4 * 32 + lane];
                    fma2(a0, h.x, wv.x); fma2(a1, h.y, wv.y);
                    ulonglong2 h2  = H[k4 + 1];
                    ulonglong2 wv2 = sW2q[(k4 + 1) * 32 + lane];
                    fma2(a2, h2.x, wv2.x); fma2(a3, h2.y, wv2.y);
                }
                float v = b2l + (hsum2(a0) + hsum2(a1)) + (hsum2(a2) + hsum2(a3));
                h2w[lane] = ftanh(v);
            }
            __syncwarp();

            // ---- layer 3 + 4, branchless (lanes >=12 have zero weights -> pr = 0) ----
            float pr;
            {
                ull a0 = 0, a1 = 0;
                const ulonglong2* H3 = (const ulonglong2*)h2w;
                #pragma unroll
                for (int k4 = 0; k4 < 6; ++k4) {
                    ulonglong2 h  = H3[k4];
                    ulonglong2 wv = sW3q[k4 * 32 + lane];
                    fma2(a0, h.x, wv.x); fma2(a1, h.y, wv.y);
                }
                pr = ftanh(b3l + hsum2(a0) + hsum2(a1)) * w4l;
            }
            // 4-stage reduce: lanes 0..15 all receive the total (only they consume it)
            pr += __shfl_xor_sync(0xffffffffu, pr, 8);
            pr += __shfl_xor_sync(0xffffffffu, pr, 4);
            pr += __shfl_xor_sync(0xffffffffu, pr, 2);
            pr += __shfl_xor_sync(0xffffffffu, pr, 1);

            float out_v = ftanh(pr + b4v);
            float delta = tgt - out_v;            // valid in lanes 0..15
            d0 = d1; d1 = d2; d2 = delta;

            if (lane == 0) {
                rowsum = fmaf(delta, delta, rowsum);
                sRing[w][3 + j] = delta;                  // own-row ring (shared)
                stRelS(sprogOwn, rowTag + j + 1);         // local release flag
                if (pubG) {
                    ringW[3 + j] = delta;                 // global ring for next-CTA consumers
                    stRelG(progMe, j + 1);
                }
            }
            __syncwarp();
        }
        if (lane == 0) sumsqd += (double)rowsum;
    }
    if (lane == 0) atomicAdd(&g_sumsq, sumsqd);

    // ---- fused finish: last real CTA writes the output ----
    __syncthreads();
    if (tid == 0) {
        __threadfence();
        unsigned prev = atomicAdd(&g_done, 1u);
        if (prev == (unsigned)(REALCTAS - 1)) {
            __threadfence();
            double s = *((volatile double*)&g_sumsq);
            out[0] = (float)sqrt(s / 875520.0);   // b*c*(h-2)*w = 8*3*190*192
        }
    }
}

extern "C" void kernel_launch(void* const* d_in, const int* in_sizes, int n_in,
                              void* d_out, int out_size) {
    const float* x  = (const float*)d_in[0];
    const float* W1 = (const float*)d_in[1];
    const float* b1 = (const float*)d_in[2];
    const float* W2 = (const float*)d_in[3];
    const float* b2 = (const float*)d_in[4];
    const float* W3 = (const float*)d_in[5];
    const float* b3 = (const float*)d_in[6];
    const float* W4 = (const float*)d_in[7];
    const float* b4 = (const float*)d_in[8];

    zero_kernel<<<512, 256>>>();
    codec_kernel<<<GRIDSZ, THREADS>>>(x, W1, b1, W2, b2, W3, b3, W4, b4, (float*)d_out);
}

// round 14
// speedup vs baseline: 2.5026x; 1.0042x over previous
#include <cuda_runtime.h>
#include <math.h>

#define CH 24          // b*c independent planes
#define HI 192
#define WI 192
#define NI 186         // interior rows/cols
#define RINGROWS 64
#define NBLK 6         // CTAs per plane
#define WARPS 8
#define THREADS (WARPS*32)
#define REALCTAS (CH*NBLK)   // 144
#define GRIDSZ 148           // >=148 to disarm low-grid issue throttle

typedef unsigned long long ull;

__device__ float  g_ring[CH * RINGROWS * WI];   // zero-padded delta rows (rows w>=5 published)
__device__ int    g_prog[CH * WI];              // per-row completed-column counters
__device__ double g_sumsq;
__device__ unsigned g_done;

__device__ __forceinline__ int ldAcqG(const int* p) {
    int v;
    asm volatile("ld.acquire.gpu.global.b32 %0, [%1];" : "=r"(v) : "l"(p) : "memory");
    return v;
}
__device__ __forceinline__ void stRelG(int* p, int v) {
    asm volatile("st.release.gpu.global.b32 [%0], %1;" :: "l"(p), "r"(v) : "memory");
}
__device__ __forceinline__ int ldAcqS(unsigned a) {
    int v;
    asm volatile("ld.acquire.cta.shared.b32 %0, [%1];" : "=r"(v) : "r"(a) : "memory");
    return v;
}
__device__ __forceinline__ void stRelS(unsigned a, int v) {
    asm volatile("st.release.cta.shared.b32 [%0], %1;" :: "r"(a), "r"(v) : "memory");
}
__device__ __forceinline__ void fma2(ull& d, ull a, ull b) {
    asm("fma.rn.f32x2 %0, %1, %2, %0;" : "+l"(d) : "l"(a), "l"(b));
}
__device__ __forceinline__ float hsum2(ull v) {
    float lo, hi;
    asm("mov.b64 {%0, %1}, %2;" : "=f"(lo), "=f"(hi) : "l"(v));
    return lo + hi;
}
__device__ __forceinline__ ull packf2(float lo, float hi) {
    ull r;
    asm("mov.b64 %0, {%1, %2};" : "=l"(r) : "f"(lo), "f"(hi));
    return r;
}
// tanh(x) = 1 - 2/(e^{2x}+1); abs err ~1e-6
__device__ __forceinline__ float ftanh(float x) {
    float e = __expf(2.0f * x);
    float r;
    asm("rcp.approx.f32 %0, %1;" : "=f"(r) : "f"(e + 1.0f));
    return fmaf(-2.0f, r, 1.0f);
}

__global__ void zero_kernel() {
    int idx = blockIdx.x * blockDim.x + threadIdx.x;
    int stride = gridDim.x * blockDim.x;
    const int n = CH * RINGROWS * WI;
    for (int i = idx; i < n; i += stride) g_ring[i] = 0.0f;
    for (int i = idx; i < CH * WI; i += stride) g_prog[i] = 0;
    if (idx == 0) { g_sumsq = 0.0; g_done = 0; }
}

__global__ __launch_bounds__(THREADS, 1)
void codec_kernel(const float* __restrict__ x,
                  const float* __restrict__ W1, const float* __restrict__ B1,
                  const float* __restrict__ W2, const float* __restrict__ B2,
                  const float* __restrict__ W3, const float* __restrict__ B3,
                  const float* __restrict__ W4, const float* __restrict__ B4,
                  float* __restrict__ out)
{
    if (blockIdx.x >= REALCTAS) return;   // throttle-disarm dummies

    __shared__ __align__(16) ulonglong2 sW1q[12 * 96];
    __shared__ __align__(16) ulonglong2 sW2q[24 * 32];
    __shared__ __align__(16) ulonglong2 sW3q[6 * 32];
    __shared__ float sB1[96], sB2[32], sB3[12], sW4[12];
    __shared__ float sB4v;
    __shared__ __align__(16) float sFeat[WARPS][48];
    __shared__ __align__(16) float sH1[WARPS][96];
    __shared__ __align__(16) float sH2[WARPS][32];
    __shared__ __align__(16) float sRing[WARPS][WI];   // per-warp current row deltas
    __shared__ int sProg[WARPS];

    const int tid = threadIdx.x;

    {
        float* f1 = (float*)sW1q;
        for (int idx = tid; idx < 48 * 96; idx += THREADS) {
            int k = idx / 96, m = idx % 96;
            f1[((k >> 2) * 96 + m) * 4 + (k & 3)] = W1[idx];
        }
        float* f2 = (float*)sW2q;
        for (int idx = tid; idx < 96 * 32; idx += THREADS) {
            int k = idx / 32, m = idx % 32;
            f2[((k >> 2) * 32 + m) * 4 + (k & 3)] = (m < 24) ? W2[k * 24 + m] : 0.0f;
        }
        float* f3 = (float*)sW3q;
        for (int idx = tid; idx < 24 * 32; idx += THREADS) {
            int k = idx / 32, m = idx % 32;
            f3[((k >> 2) * 32 + m) * 4 + (k & 3)] = (m < 12) ? W3[k * 12 + m] : 0.0f;
        }
    }
    if (tid < 96) sB1[tid] = B1[tid];
    if (tid < 32) sB2[tid] = (tid < 24) ? B2[tid] : 0.0f;
    if (tid < 12) sB3[tid] = B3[tid];
    if (tid < 12) sW4[tid] = W4[tid];
    if (tid == 0) sB4v = B4[0];
    for (int idx = tid; idx < WARPS * WI; idx += THREADS) ((float*)sRing)[idx] = 0.0f;
    if (tid < WARPS) sProg[tid] = 0;
    __syncthreads();

    const int ch   = blockIdx.x / NBLK;
    const int blk  = blockIdx.x % NBLK;
    const int w    = tid >> 5;
    const int lane = tid & 31;

    const float* xch    = x + ch * HI * WI;
    float*       ringCh = g_ring + ch * RINGROWS * WI;
    int*         progCh = g_prog + ch * WI;

    const unsigned sprogAddr = (unsigned)__cvta_generic_to_shared(&sProg[0]);
    const unsigned sprogOwn  = sprogAddr + w * 4;
    const unsigned sprogPrev = sprogAddr + (w - 1) * 4;

    float* featw = sFeat[w];
    float* h1w   = sH1[w];
    float* h2w   = sH2[w];

    const int m0 = lane, m1 = lane + 32, m2 = lane + 64;
    const float bb0 = sB1[m0], bb1 = sB1[m1], bb2 = sB1[m2];
    const float b2l = sB2[lane];
    const float b3l = (lane < 12) ? sB3[lane] : 0.0f;
    const float w4l = (lane < 12) ? sW4[lane] : 0.0f;
    const float b4v = sB4v;

    // ---- W1 chunks 0..7 (k=0..31) in registers: 48 packed f32x2 per lane ----
    ull w1r[48];
    #pragma unroll
    for (int k4 = 0; k4 < 8; ++k4) {
        #pragma unroll
        for (int mi = 0; mi < 3; ++mi) {
            int m = lane + 32 * mi;
            int k = 4 * k4;
            w1r[k4 * 6 + mi * 2 + 0] = packf2(__ldg(W1 + (k + 0) * 96 + m), __ldg(W1 + (k + 1) * 96 + m));
            w1r[k4 * 6 + mi * 2 + 1] = packf2(__ldg(W1 + (k + 2) * 96 + m), __ldg(W1 + (k + 3) * 96 + m));
        }
    }

    // ---- static tap descriptors ----
    int p1_dy = 0, p1_dx = 0;
    if (lane >= 24) { int s = lane - 24; p1_dy = (s == 7) ? 1 : 0; p1_dx = (s == 7) ? 0 : s; }
    int p2_dy = 0, p2_dx = 0;
    if (lane < 13) { int s = lane + 8; p2_dy = s / 7; p2_dx = s % 7; }

    double sumsqd = 0.0;

    for (int i = WARPS * blk + w; i < NI; i += NBLK * WARPS) {
        const float* imgP = nullptr;
        if (lane < 21)      imgP = xch + (i + lane / 7) * WI + (lane % 7);
        else if (lane < 24) imgP = xch + (i + 3) * WI + (lane - 21);

        const float* base1 = nullptr; bool tapG1 = false;
        if (lane >= 24) {
            int l = w - 3 + p1_dy;
            if (l >= 0) base1 = &sRing[l][p1_dx];
            else { base1 = ringCh + ((unsigned)(i - 3 + p1_dy) & (RINGROWS - 1)) * WI + p1_dx; tapG1 = true; }
        }
        const float* base2 = nullptr; bool tapG2 = false;
        if (lane < 13) {
            int l = w - 3 + p2_dy;
            if (l >= 0) base2 = &sRing[l][p2_dx];
            else { base2 = ringCh + ((unsigned)(i - 3 + p2_dy) & (RINGROWS - 1)) * WI + p2_dx; tapG2 = true; }
        }

        // w==0: SINGLE transitive global poll on row i-1's flag (covers i-2, i-3 by
        // release/acquire cumulativity) with slack 4 so global taps prefetch one px ahead.
        int c1 = NI + 8;
        const int* gp1 = nullptr;
        if (w == 0 && i - 1 >= 0) { gp1 = progCh + (i - 1); c1 = 0; }

        const int  sNeedBase = (i - 1) * 256;
        const int  rowTag    = i * 256;
        int*       progMe    = progCh + i;
        float*     ringW     = ringCh + ((unsigned)i & (RINGROWS - 1)) * WI;
        const float* tgtRow  = xch + (i + 3) * WI + 3;
        const bool pubG      = (w >= WARPS - 3);

        int   spc = 0;
        float d0 = 0.0f, d1 = 0.0f, d2 = 0.0f;   // deltas j-3, j-2, j-1
        float rowsum = 0.0f;
        float p1v = 0.0f, p2v = 0.0f;             // prefetched global ring taps

        for (int j = 0; j < NI; ++j) {
            // ---- hoisted independent loads ----
            float vimg = 0.0f;
            if (lane < 24) vimg = __ldg(imgP + j);
            float tgt = __ldg(tgtRow + j);

            // ---- wavefront wait ----
            if (w) {
                int nd = j + 4; if (nd > NI) nd = NI;
                int sneed = sNeedBase + nd;
                while (spc < sneed) spc = ldAcqS(sprogPrev);
            } else {
                int needG = j + 8; if (needG > NI) needG = NI;   // slack 4
                while (c1 < needG) c1 = ldAcqG(gp1);
            }

            // ---- first pixel of the row: load global-tap prefetch registers in place ----
            if (j == 0) {
                if (tapG1) p1v = __ldcg(base1);
                if (tapG2) p2v = __ldcg(base2);
            }

            // ---- gather 48 features into shared staging ----
            float v1;
            if (lane < 24)  v1 = vimg;
            else if (tapG1) v1 = p1v;
            else            v1 = base1[j];
            featw[lane] = v1;
            if (lane < 13)       featw[lane + 32] = tapG2 ? p2v : base2[j];
            else if (lane < 16)  featw[lane + 32] = (lane == 13) ? d0 : (lane == 14) ? d1 : d2;
            __syncwarp();

            // ---- layer 1: 48 -> 96; chunks 0..7 reg weights, chunks 8..11 shared ----
            ull a00 = 0, a01 = 0, a10 = 0, a11 = 0, a20 = 0, a21 = 0;
            {
                const ulonglong2* F2 = (const ulonglong2*)featw;
                #pragma unroll
                for (int k4 = 0; k4 < 8; ++k4) {
                    ulonglong2 f = F2[k4];
                    fma2(a00, f.x, w1r[k4 * 6 + 0]); fma2(a01, f.y, w1r[k4 * 6 + 1]);
                    fma2(a10, f.x, w1r[k4 * 6 + 2]); fma2(a11, f.y, w1r[k4 * 6 + 3]);
                    fma2(a20, f.x, w1r[k4 * 6 + 4]); fma2(a21, f.y, w1r[k4 * 6 + 5]);
                }
                #pragma unroll
                for (int k4 = 8; k4 < 12; ++k4) {
                    ulonglong2 f  = F2[k4];
                    ulonglong2 wa = sW1q[k4 * 96 + m0];
                    ulonglong2 wb = sW1q[k4 * 96 + m1];
                    ulonglong2 wc = sW1q[k4 * 96 + m2];
                    fma2(a00, f.x, wa.x); fma2(a01, f.y, wa.y);
                    fma2(a10, f.x, wb.x); fma2(a11, f.y, wb.y);
                    fma2(a20, f.x, wc.x); fma2(a21, f.y, wc.y);
                }
            }
            h1w[m0] = ftanh(bb0 + hsum2(a00) + hsum2(a01));
            h1w[m1] = ftanh(bb1 + hsum2(a10) + hsum2(a11));
            h1w[m2] = ftanh(bb2 + hsum2(a20) + hsum2(a21));
            __syncwarp();

            // ---- layer 2: 96 -> 24, branchless (lanes >=24 have zero weights) ----
            {
                ull a0 = 0, a1 = 0, a2 = 0, a3 = 0;
                const ulonglong2* H = (const ulonglong2*)h1w;
                #pragma unroll
                for (int k4 = 0; k4 < 24; k4 += 2) {
                    ulonglong2 h  = H[k4];
                    ulonglong2 wv = sW2q[k4 * 32 + lane];
                    fma2(a0, h.x, wv.x); fma2(a1, h.y, wv.y);
                    ulonglong2 h2  = H[k4 + 1];
                    ulonglong2 wv2 = sW2q[(k4 + 1) * 32 + lane];
                    fma2(a2, h2.x, wv2.x); fma2(a3, h2.y, wv2.y);
                }
                float v = b2l + (hsum2(a0) + hsum2(a1)) + (hsum2(a2) + hsum2(a3));
                h2w[lane] = ftanh(v);
            }
            __syncwarp();

            // ---- layer 3 + 4, branchless (lanes >=12 zero weights -> pr = 0) ----
            float pr;
            {
                ull a0 = 0, a1 = 0;
                const ulonglong2* H3 = (const ulonglong2*)h2w;
                #pragma unroll
                for (int k4 = 0; k4 < 6; ++k4) {
                    ulonglong2 h  = H3[k4];
                    ulonglong2 wv = sW3q[k4 * 32 + lane];
                    fma2(a0, h.x, wv.x); fma2(a1, h.y, wv.y);
                }
                pr = ftanh(b3l + hsum2(a0) + hsum2(a1)) * w4l;
            }
            pr += __shfl_xor_sync(0xffffffffu, pr, 8);
            pr += __shfl_xor_sync(0xffffffffu, pr, 4);
            pr += __shfl_xor_sync(0xffffffffu, pr, 2);
            pr += __shfl_xor_sync(0xffffffffu, pr, 1);

            float out_v = ftanh(pr + b4v);
            float delta = tgt - out_v;            // valid in lanes 0..15
            d0 = d1; d1 = d2; d2 = delta;

            // ---- off-chain: prefetch global ring taps for pixel j+1 ----
            // Legal: w==0 holds c1 >= j+8 (slack); w==1,2 hold transitive slack >= 7.
            if (j + 1 < NI) {
                if (tapG1) p1v = __ldcg(base1 + j + 1);
                if (tapG2) p2v = __ldcg(base2 + j + 1);
            }

            if (lane == 0) {
                rowsum = fmaf(delta, delta, rowsum);
                sRing[w][3 + j] = delta;                  // own-row ring (shared)
                stRelS(sprogOwn, rowTag + j + 1);         // local release flag
                if (pubG) {
                    ringW[3 + j] = delta;                 // global ring for next-CTA consumers
                    stRelG(progMe, j + 1);
                }
            }
            __syncwarp();
        }
        if (lane == 0) sumsqd += (double)rowsum;
    }
    if (lane == 0) atomicAdd(&g_sumsq, sumsqd);

    // ---- fused finish: last real CTA writes the output ----
    __syncthreads();
    if (tid == 0) {
        __threadfence();
        unsigned prev = atomicAdd(&g_done, 1u);
        if (prev == (unsigned)(REALCTAS - 1)) {
            __threadfence();
            double s = *((volatile double*)&g_sumsq);
            out[0] = (float)sqrt(s / 875520.0);   // b*c*(h-2)*w = 8*3*190*192
        }
    }
}

extern "C" void kernel_launch(void* const* d_in, const int* in_sizes, int n_in,
                              void* d_out, int out_size) {
    const float* x  = (const float*)d_in[0];
    const float* W1 = (const float*)d_in[1];
    const float* b1 = (const float*)d_in[2];
    const float* W2 = (const float*)d_in[3];
    const float* b2 = (const float*)d_in[4];
    const float* W3 = (const float*)d_in[5];
    const float* b3 = (const float*)d_in[6];
    const float* W4 = (const float*)d_in[7];
    const float* b4 = (const float*)d_in[8];

    zero_kernel<<<512, 256>>>();
    codec_kernel<<<GRIDSZ, THREADS>>>(x, W1, b1, W2, b2, W3, b3, W4, b4, (float*)d_out);
}

// round 15
// speedup vs baseline: 2.7018x; 1.0796x over previous
#include <cuda_runtime.h>
#include <math.h>

#define CH 24          // b*c independent planes
#define HI 192
#define WI 192
#define NI 186         // interior rows/cols
#define RINGROWS 64
#define NBLK 6         // CTAs per plane
#define WARPS 8
#define THREADS (WARPS*32)
#define REALCTAS (CH*NBLK)   // 144
#define GRIDSZ 148           // >=148 to disarm low-grid issue throttle

typedef unsigned long long ull;

__device__ float  g_ring[CH * RINGROWS * WI];   // zero-padded delta rows (rows w>=5 published)
__device__ int    g_prog[CH * WI];              // per-row completed-column counters
__device__ double g_sumsq;
__device__ unsigned g_done;

__device__ __forceinline__ int ldAcqG(const int* p) {
    int v;
    asm volatile("ld.acquire.gpu.global.b32 %0, [%1];" : "=r"(v) : "l"(p) : "memory");
    return v;
}
__device__ __forceinline__ void stRelG(int* p, int v) {
    asm volatile("st.release.gpu.global.b32 [%0], %1;" :: "l"(p), "r"(v) : "memory");
}
__device__ __forceinline__ int ldAcqS(unsigned a) {
    int v;
    asm volatile("ld.acquire.cta.shared.b32 %0, [%1];" : "=r"(v) : "r"(a) : "memory");
    return v;
}
__device__ __forceinline__ void stRelS(unsigned a, int v) {
    asm volatile("st.release.cta.shared.b32 [%0], %1;" :: "r"(a), "r"(v) : "memory");
}
__device__ __forceinline__ void fma2(ull& d, ull a, ull b) {
    asm("fma.rn.f32x2 %0, %1, %2, %0;" : "+l"(d) : "l"(a), "l"(b));
}
__device__ __forceinline__ float hsum2(ull v) {
    float lo, hi;
    asm("mov.b64 {%0, %1}, %2;" : "=f"(lo), "=f"(hi) : "l"(v));
    return lo + hi;
}
__device__ __forceinline__ ull packf2(float lo, float hi) {
    ull r;
    asm("mov.b64 %0, {%1, %2};" : "=l"(r) : "f"(lo), "f"(hi));
    return r;
}
// single-MUFU tanh (sm_75+): ~16 cy, abs err ~2^-11 — well inside 1e-3 tolerance
__device__ __forceinline__ float ftanh(float x) {
    float r;
    asm("tanh.approx.f32 %0, %1;" : "=f"(r) : "f"(x));
    return r;
}

__global__ void zero_kernel() {
    int idx = blockIdx.x * blockDim.x + threadIdx.x;
    int stride = gridDim.x * blockDim.x;
    const int n = CH * RINGROWS * WI;
    for (int i = idx; i < n; i += stride) g_ring[i] = 0.0f;
    for (int i = idx; i < CH * WI; i += stride) g_prog[i] = 0;
    if (idx == 0) { g_sumsq = 0.0; g_done = 0; }
}

__global__ __launch_bounds__(THREADS, 1)
void codec_kernel(const float* __restrict__ x,
                  const float* __restrict__ W1, const float* __restrict__ B1,
                  const float* __restrict__ W2, const float* __restrict__ B2,
                  const float* __restrict__ W3, const float* __restrict__ B3,
                  const float* __restrict__ W4, const float* __restrict__ B4,
                  float* __restrict__ out)
{
    if (blockIdx.x >= REALCTAS) return;   // throttle-disarm dummies

    __shared__ __align__(16) ulonglong2 sW1q[12 * 96];
    __shared__ __align__(16) ulonglong2 sW2q[24 * 32];
    __shared__ __align__(16) ulonglong2 sW3q[6 * 32];
    __shared__ float sB1[96], sB2[32], sB3[12], sW4[12];
    __shared__ float sB4v;
    __shared__ __align__(16) float sFeat[WARPS][48];
    __shared__ __align__(16) float sH1[WARPS][96];
    __shared__ __align__(16) float sH2[WARPS][32];
    __shared__ __align__(16) float sRing[WARPS][WI];   // per-warp current row deltas
    __shared__ int sProg[WARPS];

    const int tid = threadIdx.x;

    {
        float* f1 = (float*)sW1q;
        for (int idx = tid; idx < 48 * 96; idx += THREADS) {
            int k = idx / 96, m = idx % 96;
            f1[((k >> 2) * 96 + m) * 4 + (k & 3)] = W1[idx];
        }
        float* f2 = (float*)sW2q;
        for (int idx = tid; idx < 96 * 32; idx += THREADS) {
            int k = idx / 32, m = idx % 32;
            f2[((k >> 2) * 32 + m) * 4 + (k & 3)] = (m < 24) ? W2[k * 24 + m] : 0.0f;
        }
        float* f3 = (float*)sW3q;
        for (int idx = tid; idx < 24 * 32; idx += THREADS) {
            int k = idx / 32, m = idx % 32;
            f3[((k >> 2) * 32 + m) * 4 + (k & 3)] = (m < 12) ? W3[k * 12 + m] : 0.0f;
        }
    }
    if (tid < 96) sB1[tid] = B1[tid];
    if (tid < 32) sB2[tid] = (tid < 24) ? B2[tid] : 0.0f;
    if (tid < 12) sB3[tid] = B3[tid];
    if (tid < 12) sW4[tid] = W4[tid];
    if (tid == 0) sB4v = B4[0];
    for (int idx = tid; idx < WARPS * WI; idx += THREADS) ((float*)sRing)[idx] = 0.0f;
    if (tid < WARPS) sProg[tid] = 0;
    __syncthreads();

    const int ch   = blockIdx.x / NBLK;
    const int blk  = blockIdx.x % NBLK;
    const int w    = tid >> 5;
    const int lane = tid & 31;

    const float* xch    = x + ch * HI * WI;
    float*       ringCh = g_ring + ch * RINGROWS * WI;
    int*         progCh = g_prog + ch * WI;

    const unsigned sprogAddr = (unsigned)__cvta_generic_to_shared(&sProg[0]);
    const unsigned sprogOwn  = sprogAddr + w * 4;
    const unsigned sprogPrev = sprogAddr + (w - 1) * 4;

    float* featw = sFeat[w];
    float* h1w   = sH1[w];
    float* h2w   = sH2[w];

    const int m0 = lane, m1 = lane + 32, m2 = lane + 64;
    const float bb0 = sB1[m0], bb1 = sB1[m1], bb2 = sB1[m2];
    const float b2l = sB2[lane];
    const float b3l = (lane < 12) ? sB3[lane] : 0.0f;
    const float w4l = (lane < 12) ? sW4[lane] : 0.0f;
    const float b4v = sB4v;

    // ---- W1 chunks 0..7 (k=0..31) in registers: 48 packed f32x2 per lane ----
    ull w1r[48];
    #pragma unroll
    for (int k4 = 0; k4 < 8; ++k4) {
        #pragma unroll
        for (int mi = 0; mi < 3; ++mi) {
            int m = lane + 32 * mi;
            int k = 4 * k4;
            w1r[k4 * 6 + mi * 2 + 0] = packf2(__ldg(W1 + (k + 0) * 96 + m), __ldg(W1 + (k + 1) * 96 + m));
            w1r[k4 * 6 + mi * 2 + 1] = packf2(__ldg(W1 + (k + 2) * 96 + m), __ldg(W1 + (k + 3) * 96 + m));
        }
    }

    // ---- static tap descriptors ----
    int p1_dy = 0, p1_dx = 0;
    if (lane >= 24) { int s = lane - 24; p1_dy = (s == 7) ? 1 : 0; p1_dx = (s == 7) ? 0 : s; }
    int p2_dy = 0, p2_dx = 0;
    if (lane < 13) { int s = lane + 8; p2_dy = s / 7; p2_dx = s % 7; }

    double sumsqd = 0.0;

    for (int i = WARPS * blk + w; i < NI; i += NBLK * WARPS) {
        const float* imgP = nullptr;
        if (lane < 21)      imgP = xch + (i + lane / 7) * WI + (lane % 7);
        else if (lane < 24) imgP = xch + (i + 3) * WI + (lane - 21);

        const float* base1 = nullptr; bool tapG1 = false;
        if (lane >= 24) {
            int l = w - 3 + p1_dy;
            if (l >= 0) base1 = &sRing[l][p1_dx];
            else { base1 = ringCh + ((unsigned)(i - 3 + p1_dy) & (RINGROWS - 1)) * WI + p1_dx; tapG1 = true; }
        }
        const float* base2 = nullptr; bool tapG2 = false;
        if (lane < 13) {
            int l = w - 3 + p2_dy;
            if (l >= 0) base2 = &sRing[l][p2_dx];
            else { base2 = ringCh + ((unsigned)(i - 3 + p2_dy) & (RINGROWS - 1)) * WI + p2_dx; tapG2 = true; }
        }

        // w==0: single transitive global poll with slack 4 (prefetch-legal)
        int c1 = NI + 8;
        const int* gp1 = nullptr;
        if (w == 0 && i - 1 >= 0) { gp1 = progCh + (i - 1); c1 = 0; }

        const int  sNeedBase = (i - 1) * 256;
        const int  rowTag    = i * 256;
        int*       progMe    = progCh + i;
        float*     ringW     = ringCh + ((unsigned)i & (RINGROWS - 1)) * WI;
        const float* tgtRow  = xch + (i + 3) * WI + 3;
        const bool pubG      = (w >= WARPS - 3);

        int   spc = 0;
        float d0 = 0.0f, d1 = 0.0f, d2 = 0.0f;   // deltas j-3, j-2, j-1
        float rowsum = 0.0f;
        float p1v = 0.0f, p2v = 0.0f;             // prefetched global ring taps

        for (int j = 0; j < NI; ++j) {
            // ---- hoisted independent loads ----
            float vimg = 0.0f;
            if (lane < 24) vimg = __ldg(imgP + j);
            float tgt = __ldg(tgtRow + j);

            // ---- wavefront wait ----
            if (w) {
                int nd = j + 4; if (nd > NI) nd = NI;
                int sneed = sNeedBase + nd;
                while (spc < sneed) spc = ldAcqS(sprogPrev);
            } else {
                int needG = j + 8; if (needG > NI) needG = NI;   // slack 4
                while (c1 < needG) c1 = ldAcqG(gp1);
            }

            if (j == 0) {
                if (tapG1) p1v = __ldcg(base1);
                if (tapG2) p2v = __ldcg(base2);
            }

            // ---- gather 48 features into shared staging ----
            float v1;
            if (lane < 24)  v1 = vimg;
            else if (tapG1) v1 = p1v;
            else            v1 = base1[j];
            featw[lane] = v1;
            if (lane < 13)       featw[lane + 32] = tapG2 ? p2v : base2[j];
            else if (lane < 16)  featw[lane + 32] = (lane == 13) ? d0 : (lane == 14) ? d1 : d2;
            __syncwarp();

            // ---- layer 1: 48 -> 96; chunks 0..7 reg weights, chunks 8..11 shared ----
            ull a00 = 0, a01 = 0, a10 = 0, a11 = 0, a20 = 0, a21 = 0;
            {
                const ulonglong2* F2 = (const ulonglong2*)featw;
                #pragma unroll
                for (int k4 = 0; k4 < 8; ++k4) {
                    ulonglong2 f = F2[k4];
                    fma2(a00, f.x, w1r[k4 * 6 + 0]); fma2(a01, f.y, w1r[k4 * 6 + 1]);
                    fma2(a10, f.x, w1r[k4 * 6 + 2]); fma2(a11, f.y, w1r[k4 * 6 + 3]);
                    fma2(a20, f.x, w1r[k4 * 6 + 4]); fma2(a21, f.y, w1r[k4 * 6 + 5]);
                }
                #pragma unroll
                for (int k4 = 8; k4 < 12; ++k4) {
                    ulonglong2 f  = F2[k4];
                    ulonglong2 wa = sW1q[k4 * 96 + m0];
                    ulonglong2 wb = sW1q[k4 * 96 + m1];
                    ulonglong2 wc = sW1q[k4 * 96 + m2];
                    fma2(a00, f.x, wa.x); fma2(a01, f.y, wa.y);
                    fma2(a10, f.x, wb.x); fma2(a11, f.y, wb.y);
                    fma2(a20, f.x, wc.x); fma2(a21, f.y, wc.y);
                }
            }
            h1w[m0] = ftanh(bb0 + hsum2(a00) + hsum2(a01));
            h1w[m1] = ftanh(bb1 + hsum2(a10) + hsum2(a11));
            h1w[m2] = ftanh(bb2 + hsum2(a20) + hsum2(a21));
            __syncwarp();

            // ---- layer 2: 96 -> 24, branchless (lanes >=24 zero weights) ----
            {
                ull a0 = 0, a1 = 0, a2 = 0, a3 = 0;
                const ulonglong2* H = (const ulonglong2*)h1w;
                #pragma unroll
                for (int k4 = 0; k4 < 24; k4 += 2) {
                    ulonglong2 h  = H[k4];
                    ulonglong2 wv = sW2q[k4 * 32 + lane];
                    fma2(a0, h.x, wv.x); fma2(a1, h.y, wv.y);
                    ulonglong2 h2  = H[k4 + 1];
                    ulonglong2 wv2 = sW2q[(k4 + 1) * 32 + lane];
                    fma2(a2, h2.x, wv2.x); fma2(a3, h2.y, wv2.y);
                }
                float v = b2l + (hsum2(a0) + hsum2(a1)) + (hsum2(a2) + hsum2(a3));
                h2w[lane] = ftanh(v);
            }
            __syncwarp();

            // ---- layer 3 + 4, branchless (lanes >=12 zero weights -> pr = 0) ----
            float pr;
            {
                ull a0 = 0, a1 = 0;
                const ulonglong2* H3 = (const ulonglong2*)h2w;
                #pragma unroll
                for (int k4 = 0; k4 < 6; ++k4) {
                    ulonglong2 h  = H3[k4];
                    ulonglong2 wv = sW3q[k4 * 32 + lane];
                    fma2(a0, h.x, wv.x); fma2(a1, h.y, wv.y);
                }
                pr = ftanh(b3l + hsum2(a0) + hsum2(a1)) * w4l;
            }
            pr += __shfl_xor_sync(0xffffffffu, pr, 8);
            pr += __shfl_xor_sync(0xffffffffu, pr, 4);
            pr += __shfl_xor_sync(0xffffffffu, pr, 2);
            pr += __shfl_xor_sync(0xffffffffu, pr, 1);

            float out_v = ftanh(pr + b4v);
            float delta = tgt - out_v;            // valid in lanes 0..15
            d0 = d1; d1 = d2; d2 = delta;

            // ---- off-chain: prefetch global ring taps for pixel j+1 ----
            if (j + 1 < NI) {
                if (tapG1) p1v = __ldcg(base1 + j + 1);
                if (tapG2) p2v = __ldcg(base2 + j + 1);
            }

            if (lane == 0) {
                rowsum = fmaf(delta, delta, rowsum);
                sRing[w][3 + j] = delta;                  // own-row ring (shared)
                stRelS(sprogOwn, rowTag + j + 1);         // local release flag
                if (pubG) {
                    ringW[3 + j] = delta;                 // global ring for next-CTA consumers
                    stRelG(progMe, j + 1);
                }
            }
            __syncwarp();
        }
        if (lane == 0) sumsqd += (double)rowsum;
    }
    if (lane == 0) atomicAdd(&g_sumsq, sumsqd);

    // ---- fused finish: last real CTA writes the output ----
    __syncthreads();
    if (tid == 0) {
        __threadfence();
        unsigned prev = atomicAdd(&g_done, 1u);
        if (prev == (unsigned)(REALCTAS - 1)) {
            __threadfence();
            double s = *((volatile double*)&g_sumsq);
            out[0] = (float)sqrt(s / 875520.0);   // b*c*(h-2)*w = 8*3*190*192
        }
    }
}

extern "C" void kernel_launch(void* const* d_in, const int* in_sizes, int n_in,
                              void* d_out, int out_size) {
    const float* x  = (const float*)d_in[0];
    const float* W1 = (const float*)d_in[1];
    const float* b1 = (const float*)d_in[2];
    const float* W2 = (const float*)d_in[3];
    const float* b2 = (const float*)d_in[4];
    const float* W3 = (const float*)d_in[5];
    const float* b3 = (const float*)d_in[6];
    const float* W4 = (const float*)d_in[7];
    const float* b4 = (const float*)d_in[8];

    zero_kernel<<<512, 256>>>();
    codec_kernel<<<GRIDSZ, THREADS>>>(x, W1, b1, W2, b2, W3, b3, W4, b4, (float*)d_out);
}

// round 17
// speedup vs baseline: 2.7928x; 1.0337x over previous
#include <cuda_runtime.h>
#include <math.h>

#define CH 24          // b*c independent planes
#define HI 192
#define WI 192
#define NI 186         // interior rows/cols
#define RINGROWS 64
#define NBLK 6         // CTAs per plane
#define WARPS 8
#define THREADS (WARPS*32)
#define REALCTAS (CH*NBLK)   // 144
#define GRIDSZ 148           // >=148 to disarm low-grid issue throttle

typedef unsigned long long ull;

__device__ float  g_ring[CH * RINGROWS * WI];   // zero-padded delta rows (rows w>=5 published)
__device__ int    g_prog[CH * WI];              // per-row completed-column counters
__device__ double g_sumsq;
__device__ unsigned g_done;

__device__ __forceinline__ int ldAcqG(const int* p) {
    int v;
    asm volatile("ld.acquire.gpu.global.b32 %0, [%1];" : "=r"(v) : "l"(p) : "memory");
    return v;
}
__device__ __forceinline__ void stRelG(int* p, int v) {
    asm volatile("st.release.gpu.global.b32 [%0], %1;" :: "l"(p), "r"(v) : "memory");
}
__device__ __forceinline__ int ldAcqS(unsigned a) {
    int v;
    asm volatile("ld.acquire.cta.shared.b32 %0, [%1];" : "=r"(v) : "r"(a) : "memory");
    return v;
}
__device__ __forceinline__ void stRelS(unsigned a, int v) {
    asm volatile("st.release.cta.shared.b32 [%0], %1;" :: "r"(a), "r"(v) : "memory");
}
__device__ __forceinline__ void fma2(ull& d, ull a, ull b) {
    asm("fma.rn.f32x2 %0, %1, %2, %0;" : "+l"(d) : "l"(a), "l"(b));
}
__device__ __forceinline__ float hsum2(ull v) {
    float lo, hi;
    asm("mov.b64 {%0, %1}, %2;" : "=f"(lo), "=f"(hi) : "l"(v));
    return lo + hi;
}
__device__ __forceinline__ ull packf2(float lo, float hi) {
    ull r;
    asm("mov.b64 %0, {%1, %2};" : "=l"(r) : "f"(lo), "f"(hi));
    return r;
}
// single-MUFU tanh (sm_75+): ~16 cy, abs err ~2^-11 — well inside 1e-3 tolerance
__device__ __forceinline__ float ftanh(float x) {
    float r;
    asm("tanh.approx.f32 %0, %1;" : "=f"(r) : "f"(x));
    return r;
}

__global__ void zero_kernel() {
    int idx = blockIdx.x * blockDim.x + threadIdx.x;
    int stride = gridDim.x * blockDim.x;
    const int n = CH * RINGROWS * WI;
    for (int i = idx; i < n; i += stride) g_ring[i] = 0.0f;
    for (int i = idx; i < CH * WI; i += stride) g_prog[i] = 0;
    if (idx == 0) { g_sumsq = 0.0; g_done = 0; }
}

__global__ __launch_bounds__(THREADS, 1)
void codec_kernel(const float* __restrict__ x,
                  const float* __restrict__ W1, const float* __restrict__ B1,
                  const float* __restrict__ W2, const float* __restrict__ B2,
                  const float* __restrict__ W3, const float* __restrict__ B3,
                  const float* __restrict__ W4, const float* __restrict__ B4,
                  float* __restrict__ out)
{
    if (blockIdx.x >= REALCTAS) return;   // throttle-disarm dummies

    __shared__ __align__(16) ulonglong2 sW1q[12 * 96];
    __shared__ __align__(16) ulonglong2 sW2q[24 * 32];
    __shared__ __align__(16) ulonglong2 sW3q[6 * 32];
    __shared__ float sB1[96], sB2[32], sB3[12], sW4[12];
    __shared__ float sB4v;
    __shared__ __align__(16) float sFeat[WARPS][48];
    __shared__ __align__(16) float sH1[WARPS][96];
    __shared__ __align__(16) float sH2[WARPS][32];
    __shared__ __align__(16) float sRing[WARPS][WI];   // per-warp current row deltas
    __shared__ int sProg[WARPS];

    const int tid = threadIdx.x;

    {
        float* f1 = (float*)sW1q;
        for (int idx = tid; idx < 48 * 96; idx += THREADS) {
            int k = idx / 96, m = idx % 96;
            f1[((k >> 2) * 96 + m) * 4 + (k & 3)] = W1[idx];
        }
        float* f2 = (float*)sW2q;
        for (int idx = tid; idx < 96 * 32; idx += THREADS) {
            int k = idx / 32, m = idx % 32;
            f2[((k >> 2) * 32 + m) * 4 + (k & 3)] = (m < 24) ? W2[k * 24 + m] : 0.0f;
        }
        float* f3 = (float*)sW3q;
        for (int idx = tid; idx < 24 * 32; idx += THREADS) {
            int k = idx / 32, m = idx % 32;
            f3[((k >> 2) * 32 + m) * 4 + (k & 3)] = (m < 12) ? W3[k * 12 + m] : 0.0f;
        }
    }
    if (tid < 96) sB1[tid] = B1[tid];
    if (tid < 32) sB2[tid] = (tid < 24) ? B2[tid] : 0.0f;
    if (tid < 12) sB3[tid] = B3[tid];
    if (tid < 12) sW4[tid] = W4[tid];
    if (tid == 0) sB4v = B4[0];
    for (int idx = tid; idx < WARPS * WI; idx += THREADS) ((float*)sRing)[idx] = 0.0f;
    if (tid < WARPS) sProg[tid] = 0;
    __syncthreads();

    const int ch   = blockIdx.x / NBLK;
    const int blk  = blockIdx.x % NBLK;
    const int w    = tid >> 5;
    const int lane = tid & 31;

    const float* xch    = x + ch * HI * WI;
    float*       ringCh = g_ring + ch * RINGROWS * WI;
    int*         progCh = g_prog + ch * WI;

    const unsigned sprogAddr = (unsigned)__cvta_generic_to_shared(&sProg[0]);
    const unsigned sprogOwn  = sprogAddr + w * 4;
    const unsigned sprogPrev = sprogAddr + (w - 1) * 4;

    float* featw = sFeat[w];
    float* h1w   = sH1[w];
    float* h2w   = sH2[w];

    const int m0 = lane, m1 = lane + 32, m2 = lane + 64;
    const float bb0 = sB1[m0], bb1 = sB1[m1], bb2 = sB1[m2];
    const float b2l = sB2[lane];
    const float b3l = (lane < 12) ? sB3[lane] : 0.0f;
    const float w4l = (lane < 12) ? sW4[lane] : 0.0f;
    const float b4v = sB4v;

    // ---- W1 chunks 0..6 (k=0..27) in registers: 42 packed f32x2 per lane ----
    ull w1r[42];
    #pragma unroll
    for (int k4 = 0; k4 < 7; ++k4) {
        #pragma unroll
        for (int mi = 0; mi < 3; ++mi) {
            int m = lane + 32 * mi;
            int k = 4 * k4;
            w1r[k4 * 6 + mi * 2 + 0] = packf2(__ldg(W1 + (k + 0) * 96 + m), __ldg(W1 + (k + 1) * 96 + m));
            w1r[k4 * 6 + mi * 2 + 1] = packf2(__ldg(W1 + (k + 2) * 96 + m), __ldg(W1 + (k + 3) * 96 + m));
        }
    }
    // ---- W1 chunk 11 (k=44..47: tap44 + last-3 deltas) in registers: recurrence bypass ----
    ull w1T[6];
    #pragma unroll
    for (int mi = 0; mi < 3; ++mi) {
        int m = lane + 32 * mi;
        w1T[mi * 2 + 0] = packf2(__ldg(W1 + 44 * 96 + m), __ldg(W1 + 45 * 96 + m));
        w1T[mi * 2 + 1] = packf2(__ldg(W1 + 46 * 96 + m), __ldg(W1 + 47 * 96 + m));
    }

    // ---- static tap descriptors ----
    int p1_dy = 0, p1_dx = 0;
    if (lane >= 24) { int s = lane - 24; p1_dy = (s == 7) ? 1 : 0; p1_dx = (s == 7) ? 0 : s; }
    int p2_dy = 0, p2_dx = 0;
    if (lane < 13) { int s = lane + 8; p2_dy = s / 7; p2_dx = s % 7; }

    double sumsqd = 0.0;

    for (int i = WARPS * blk + w; i < NI; i += NBLK * WARPS) {
        const float* imgP = nullptr;
        if (lane < 21)      imgP = xch + (i + lane / 7) * WI + (lane % 7);
        else if (lane < 24) imgP = xch + (i + 3) * WI + (lane - 21);

        const float* base1 = nullptr; bool tapG1 = false;
        if (lane >= 24) {
            int l = w - 3 + p1_dy;
            if (l >= 0) base1 = &sRing[l][p1_dx];
            else { base1 = ringCh + ((unsigned)(i - 3 + p1_dy) & (RINGROWS - 1)) * WI + p1_dx; tapG1 = true; }
        }
        const float* base2 = nullptr; bool tapG2 = false;
        if (lane < 13) {
            int l = w - 3 + p2_dy;
            if (l >= 0) base2 = &sRing[l][p2_dx];
            else { base2 = ringCh + ((unsigned)(i - 3 + p2_dy) & (RINGROWS - 1)) * WI + p2_dx; tapG2 = true; }
        }

        // w==0: single transitive global poll with slack 4 (prefetch-legal)
        int c1 = NI + 8;
        const int* gp1 = nullptr;
        if (w == 0 && i - 1 >= 0) { gp1 = progCh + (i - 1); c1 = 0; }

        const int  sNeedBase = (i - 1) * 256;
        const int  rowTag    = i * 256;
        int*       progMe    = progCh + i;
        float*     ringW     = ringCh + ((unsigned)i & (RINGROWS - 1)) * WI;
        const float* tgtRow  = xch + (i + 3) * WI + 3;
        const bool pubG      = (w >= WARPS - 3);

        int   spc = 0;
        float d0 = 0.0f, d1 = 0.0f, d2 = 0.0f;   // deltas j-3, j-2, j-1 (all lanes, exact)
        float rowsum = 0.0f;
        float p1v = 0.0f, p2v = 0.0f;             // prefetched global ring taps

        for (int j = 0; j < NI; ++j) {
            // ---- hoisted independent loads ----
            float vimg = 0.0f;
            if (lane < 24) vimg = __ldg(imgP + j);
            float tgt = __ldg(tgtRow + j);

            // ---- wavefront wait ----
            if (w) {
                int nd = j + 4; if (nd > NI) nd = NI;
                int sneed = sNeedBase + nd;
                while (spc < sneed) spc = ldAcqS(sprogPrev);
            } else {
                int needG = j + 8; if (needG > NI) needG = NI;   // slack 4
                while (c1 < needG) c1 = ldAcqG(gp1);
            }

            if (j == 0) {
                if (tapG1) p1v = __ldcg(base1);
                if (tapG2) p2v = __ldcg(base2);
            }

            // ---- gather feats 0..44 into shared staging (45..47 stay in regs) ----
            float v1;
            if (lane < 24)  v1 = vimg;
            else if (tapG1) v1 = p1v;
            else            v1 = base1[j];
            featw[lane] = v1;
            if (lane < 13) featw[lane + 32] = tapG2 ? p2v : base2[j];
            __syncwarp();
            float f44 = featw[44];   // broadcast

            // ---- layer 1: 48 -> 96; chunks 0..6 reg, 7..10 shared, 11 reg (recurrence) ----
            ull a00 = 0, a01 = 0, a10 = 0, a11 = 0, a20 = 0, a21 = 0;
            {
                const ulonglong2* F2 = (const ulonglong2*)featw;
                #pragma unroll
                for (int k4 = 0; k4 < 7; ++k4) {
                    ulonglong2 f = F2[k4];
                    fma2(a00, f.x, w1r[k4 * 6 + 0]); fma2(a01, f.y, w1r[k4 * 6 + 1]);
                    fma2(a10, f.x, w1r[k4 * 6 + 2]); fma2(a11, f.y, w1r[k4 * 6 + 3]);
                    fma2(a20, f.x, w1r[k4 * 6 + 4]); fma2(a21, f.y, w1r[k4 * 6 + 5]);
                }
                #pragma unroll
                for (int k4 = 7; k4 < 11; ++k4) {
                    ulonglong2 f  = F2[k4];
                    ulonglong2 wa = sW1q[k4 * 96 + m0];
                    ulonglong2 wb = sW1q[k4 * 96 + m1];
                    ulonglong2 wc = sW1q[k4 * 96 + m2];
                    fma2(a00, f.x, wa.x); fma2(a01, f.y, wa.y);
                    fma2(a10, f.x, wb.x); fma2(a11, f.y, wb.y);
                    fma2(a20, f.x, wc.x); fma2(a21, f.y, wc.y);
                }
                // chunk 11: (f44, d0) and (d1, d2) — pure register path
                ull fa = packf2(f44, d0);
                ull fb = packf2(d1, d2);
                fma2(a00, fa, w1T[0]); fma2(a01, fb, w1T[1]);
                fma2(a10, fa, w1T[2]); fma2(a11, fb, w1T[3]);
                fma2(a20, fa, w1T[4]); fma2(a21, fb, w1T[5]);
            }
            h1w[m0] = ftanh(bb0 + hsum2(a00) + hsum2(a01));
            h1w[m1] = ftanh(bb1 + hsum2(a10) + hsum2(a11));
            h1w[m2] = ftanh(bb2 + hsum2(a20) + hsum2(a21));
            __syncwarp();

            // ---- layer 2: 96 -> 24, branchless (lanes >=24 zero weights) ----
            {
                ull a0 = 0, a1 = 0, a2 = 0, a3 = 0;
                const ulonglong2* H = (const ulonglong2*)h1w;
                #pragma unroll
                for (int k4 = 0; k4 < 24; k4 += 2) {
                    ulonglong2 h  = H[k4];
                    ulonglong2 wv = sW2q[k4 * 32 + lane];
                    fma2(a0, h.x, wv.x); fma2(a1, h.y, wv.y);
                    ulonglong2 h2  = H[k4 + 1];
                    ulonglong2 wv2 = sW2q[(k4 + 1) * 32 + lane];
                    fma2(a2, h2.x, wv2.x); fma2(a3, h2.y, wv2.y);
                }
                float v = b2l + (hsum2(a0) + hsum2(a1)) + (hsum2(a2) + hsum2(a3));
                h2w[lane] = ftanh(v);
            }
            __syncwarp();

            // ---- layer 3 + 4, branchless (lanes >=12 zero weights -> pr = 0) ----
            float pr;
            {
                ull a0 = 0, a1 = 0;
                const ulonglong2* H3 = (const ulonglong2*)h2w;
                #pragma unroll
                for (int k4 = 0; k4 < 6; ++k4) {
                    ulonglong2 h  = H3[k4];
                    ulonglong2 wv = sW3q[k4 * 32 + lane];
                    fma2(a0, h.x, wv.x); fma2(a1, h.y, wv.y);
                }
                pr = ftanh(b3l + hsum2(a0) + hsum2(a1)) * w4l;
            }
            // 5-stage reduce: ALL 32 lanes receive the full sum (chunk-11 bypass
            // consumes d0..d2 in every lane, so delta must be exact everywhere)
            pr += __shfl_xor_sync(0xffffffffu, pr, 16);
            pr += __shfl_xor_sync(0xffffffffu, pr, 8);
            pr += __shfl_xor_sync(0xffffffffu, pr, 4);
            pr += __shfl_xor_sync(0xffffffffu, pr, 2);
            pr += __shfl_xor_sync(0xffffffffu, pr, 1);

            float out_v = ftanh(pr + b4v);
            float delta = tgt - out_v;            // exact in all lanes
            d0 = d1; d1 = d2; d2 = delta;

            // ---- publish ASAP (consumer discovery latency) ----
            if (lane == 0) {
                sRing[w][3 + j] = delta;                  // own-row ring (shared)
                stRelS(sprogOwn, rowTag + j + 1);         // local release flag
                if (pubG) {
                    ringW[3 + j] = delta;                 // global ring for next-CTA consumers
                    stRelG(progMe, j + 1);
                }
                rowsum = fmaf(delta, delta, rowsum);
            }

            // ---- off-chain: prefetch global ring taps for pixel j+1 ----
            if (j + 1 < NI) {
                if (tapG1) p1v = __ldcg(base1 + j + 1);
                if (tapG2) p2v = __ldcg(base2 + j + 1);
            }
            __syncwarp();
        }
        if (lane == 0) sumsqd += (double)rowsum;
    }
    if (lane == 0) atomicAdd(&g_sumsq, sumsqd);

    // ---- fused finish: last real CTA writes the output ----
    __syncthreads();
    if (tid == 0) {
        __threadfence();
        unsigned prev = atomicAdd(&g_done, 1u);
        if (prev == (unsigned)(REALCTAS - 1)) {
            __threadfence();
            double s = *((volatile double*)&g_sumsq);
            out[0] = (float)sqrt(s / 875520.0);   // b*c*(h-2)*w = 8*3*190*192
        }
    }
}

extern "C" void kernel_launch(void* const* d_in, const int* in_sizes, int n_in,
                              void* d_out, int out_size) {
    const float* x  = (const float*)d_in[0];
    const float* W1 = (const float*)d_in[1];
    const float* b1 = (const float*)d_in[2];
    const float* W2 = (const float*)d_in[3];
    const float* b2 = (const float*)d_in[4];
    const float* W3 = (const float*)d_in[5];
    const float* b3 = (const float*)d_in[6];
    const float* W4 = (const float*)d_in[7];
    const float* b4 = (const float*)d_in[8];

    zero_kernel<<<512, 256>>>();
    codec_kernel<<<GRIDSZ, THREADS>>>(x, W1, b1, W2, b2, W3, b3, W4, b4, (float*)d_out);
}